// round 4
// baseline (speedup 1.0000x reference)
#include <cuda_runtime.h>
#include <math.h>

#define D_MODEL 1024
#define N_HEAD  16
#define D_HEAD  64
#define B_      2
#define T_      2048
#define M_TOK   (B_ * T_)          // 4096
#define N_QKV   (3 * N_HEAD * D_HEAD)  // 3072

// ---------------- scratch (device globals; no allocation allowed) ------------
__device__ float g_q[B_ * N_HEAD * T_ * D_HEAD];   // (B,H,T,dh) 16MB
__device__ float g_k[B_ * N_HEAD * T_ * D_HEAD];
__device__ float g_v[B_ * N_HEAD * T_ * D_HEAD];
__device__ float g_ov[M_TOK * D_MODEL];            // attn_vec in (B,T,H*dh)
__device__ float g_y[M_TOK * D_MODEL];             // inp + attn_out

// ---------------- QKV GEMM: C[m,o] = inp[m,:] . W_qkv[o,:] + b[o] ------------
// 128x128x16 tiles, 256 threads, 8x8 per thread. Epilogue scatters to q/k/v.
__global__ __launch_bounds__(256) void qkv_gemm(const float* __restrict__ A,
                                                const float* __restrict__ W,
                                                const float* __restrict__ bias) {
    __shared__ float As[16][132];
    __shared__ float Bs[16][132];
    const int tid = threadIdx.x;
    const int m0 = blockIdx.y * 128;
    const int n0 = blockIdx.x * 128;
    const int ty = tid >> 4;
    const int tx = tid & 15;
    const int lr = tid >> 2;          // 0..63
    const int lc = (tid & 3) << 2;    // 0,4,8,12

    float acc[8][8];
#pragma unroll
    for (int i = 0; i < 8; i++)
#pragma unroll
        for (int j = 0; j < 8; j++) acc[i][j] = 0.f;

    for (int kt = 0; kt < D_MODEL; kt += 16) {
#pragma unroll
        for (int rr = 0; rr < 2; rr++) {
            const int r = lr + rr * 64;
            float4 a4 = *(const float4*)(A + (size_t)(m0 + r) * D_MODEL + kt + lc);
            As[lc + 0][r] = a4.x; As[lc + 1][r] = a4.y;
            As[lc + 2][r] = a4.z; As[lc + 3][r] = a4.w;
            float4 b4 = *(const float4*)(W + (size_t)(n0 + r) * D_MODEL + kt + lc);
            Bs[lc + 0][r] = b4.x; Bs[lc + 1][r] = b4.y;
            Bs[lc + 2][r] = b4.z; Bs[lc + 3][r] = b4.w;
        }
        __syncthreads();
#pragma unroll
        for (int k = 0; k < 16; k++) {
            float a[8], b[8];
            *(float4*)(a)     = *(const float4*)&As[k][ty * 8];
            *(float4*)(a + 4) = *(const float4*)&As[k][ty * 8 + 4];
            *(float4*)(b)     = *(const float4*)&Bs[k][tx * 8];
            *(float4*)(b + 4) = *(const float4*)&Bs[k][tx * 8 + 4];
#pragma unroll
            for (int i = 0; i < 8; i++)
#pragma unroll
                for (int j = 0; j < 8; j++)
                    acc[i][j] = fmaf(a[i], b[j], acc[i][j]);
        }
        __syncthreads();
    }

#pragma unroll
    for (int i = 0; i < 8; i++) {
        const int m = m0 + ty * 8 + i;
        const int b = m >> 11;          // /T_
        const int t = m & (T_ - 1);
#pragma unroll
        for (int j = 0; j < 8; j++) {
            const int o = n0 + tx * 8 + j;
            const float c = acc[i][j] + bias[o];
            const int part = o >> 10;       // 0=q 1=k 2=v
            const int rem = o & 1023;
            const int h = rem >> 6;
            const int d = rem & 63;
            const int idx = ((b * N_HEAD + h) * T_ + t) * D_HEAD + d;
            if (part == 0)      g_q[idx] = c;
            else if (part == 1) g_k[idx] = c;
            else                g_v[idx] = c;
        }
    }
}

// ---------------- O-proj GEMM: y[m,o] = ov[m,:] . W_o[o,:] + inp[m,o] --------
__global__ __launch_bounds__(256) void o_gemm(const float* __restrict__ Wo,
                                              const float* __restrict__ inp) {
    __shared__ float As[16][132];
    __shared__ float Bs[16][132];
    const int tid = threadIdx.x;
    const int m0 = blockIdx.y * 128;
    const int n0 = blockIdx.x * 128;
    const int ty = tid >> 4;
    const int tx = tid & 15;
    const int lr = tid >> 2;
    const int lc = (tid & 3) << 2;

    float acc[8][8];
#pragma unroll
    for (int i = 0; i < 8; i++)
#pragma unroll
        for (int j = 0; j < 8; j++) acc[i][j] = 0.f;

    for (int kt = 0; kt < D_MODEL; kt += 16) {
#pragma unroll
        for (int rr = 0; rr < 2; rr++) {
            const int r = lr + rr * 64;
            float4 a4 = *(const float4*)(g_ov + (size_t)(m0 + r) * D_MODEL + kt + lc);
            As[lc + 0][r] = a4.x; As[lc + 1][r] = a4.y;
            As[lc + 2][r] = a4.z; As[lc + 3][r] = a4.w;
            float4 b4 = *(const float4*)(Wo + (size_t)(n0 + r) * D_MODEL + kt + lc);
            Bs[lc + 0][r] = b4.x; Bs[lc + 1][r] = b4.y;
            Bs[lc + 2][r] = b4.z; Bs[lc + 3][r] = b4.w;
        }
        __syncthreads();
#pragma unroll
        for (int k = 0; k < 16; k++) {
            float a[8], b[8];
            *(float4*)(a)     = *(const float4*)&As[k][ty * 8];
            *(float4*)(a + 4) = *(const float4*)&As[k][ty * 8 + 4];
            *(float4*)(b)     = *(const float4*)&Bs[k][tx * 8];
            *(float4*)(b + 4) = *(const float4*)&Bs[k][tx * 8 + 4];
#pragma unroll
            for (int i = 0; i < 8; i++)
#pragma unroll
                for (int j = 0; j < 8; j++)
                    acc[i][j] = fmaf(a[i], b[j], acc[i][j]);
        }
        __syncthreads();
    }

#pragma unroll
    for (int i = 0; i < 8; i++) {
        const int m = m0 + ty * 8 + i;
#pragma unroll
        for (int j = 0; j < 8; j++) {
            const int o = n0 + tx * 8 + j;
            const size_t idx = (size_t)m * D_MODEL + o;
            g_y[idx] = acc[i][j] + inp[idx];
        }
    }
}

// ---------------- Flash attention per (b,h), 64-query blocks -----------------
// smem: Qs[64][64] | Ks[64][65] (reused as P) | Vs[64][64]
#define SMEM_ATTN ((64 * 64 + 64 * 65 + 64 * 64) * 4)

__global__ __launch_bounds__(256) void attn_kernel() {
    extern __shared__ float sm[];
    float* Qs = sm;                  // stride 64
    float* Ks = sm + 64 * 64;        // stride 65, aliased as P
    float* Vs = Ks + 64 * 65;        // stride 64

    const int bh = blockIdx.y;       // = b*16 + h
    const int qb = blockIdx.x * 64;
    const float* Qg = g_q + (size_t)bh * T_ * D_HEAD;
    const float* Kg = g_k + (size_t)bh * T_ * D_HEAD;
    const float* Vg = g_v + (size_t)bh * T_ * D_HEAD;

    const int tid = threadIdx.x;
    const int ty = tid >> 4;         // 0..15 -> query strides
    const int tx = tid & 15;         // 0..15 -> key/dh strides
    const int lr = tid >> 4;         // load row base
    const int lc = (tid & 15) * 4;   // load col (float4)

    // load Q tile (64x64)
#pragma unroll
    for (int rr = 0; rr < 4; rr++) {
        const int r = lr + rr * 16;
        float4 q4 = *(const float4*)(Qg + (size_t)(qb + r) * D_HEAD + lc);
        *(float4*)&Qs[r * 64 + lc] = q4;
    }

    float acc[4][4];
    float mi[4], li[4];
#pragma unroll
    for (int i = 0; i < 4; i++) {
        mi[i] = -1e30f; li[i] = 0.f;
#pragma unroll
        for (int j = 0; j < 4; j++) acc[i][j] = 0.f;
    }
    const float scale = 0.125f;      // 1/sqrt(64)

    for (int kb = 0; kb < T_; kb += 64) {
        __syncthreads();             // previous P/V reads done
#pragma unroll
        for (int rr = 0; rr < 4; rr++) {
            const int r = lr + rr * 16;
            float4 k4 = *(const float4*)(Kg + (size_t)(kb + r) * D_HEAD + lc);
            Ks[r * 65 + lc + 0] = k4.x; Ks[r * 65 + lc + 1] = k4.y;
            Ks[r * 65 + lc + 2] = k4.z; Ks[r * 65 + lc + 3] = k4.w;
            float4 v4 = *(const float4*)(Vg + (size_t)(kb + r) * D_HEAD + lc);
            *(float4*)&Vs[r * 64 + lc] = v4;
        }
        __syncthreads();

        // S = Q @ K^T
        float s[4][4];
#pragma unroll
        for (int i = 0; i < 4; i++)
#pragma unroll
            for (int j = 0; j < 4; j++) s[i][j] = 0.f;
#pragma unroll 4
        for (int d = 0; d < 64; d++) {
            float qv[4], kv[4];
#pragma unroll
            for (int i = 0; i < 4; i++) qv[i] = Qs[(ty + 16 * i) * 64 + d];
#pragma unroll
            for (int j = 0; j < 4; j++) kv[j] = Ks[(tx + 16 * j) * 65 + d];
#pragma unroll
            for (int i = 0; i < 4; i++)
#pragma unroll
                for (int j = 0; j < 4; j++)
                    s[i][j] = fmaf(qv[i], kv[j], s[i][j]);
        }

        // online softmax (16-lane groups == same query rows)
#pragma unroll
        for (int i = 0; i < 4; i++) {
            float mx = -1e30f;
#pragma unroll
            for (int j = 0; j < 4; j++) {
                s[i][j] *= scale;
                mx = fmaxf(mx, s[i][j]);
            }
#pragma unroll
            for (int o = 8; o; o >>= 1)
                mx = fmaxf(mx, __shfl_xor_sync(0xffffffffu, mx, o, 16));
            const float mnew = fmaxf(mi[i], mx);
            const float alpha = __expf(mi[i] - mnew);
            float rs = 0.f;
#pragma unroll
            for (int j = 0; j < 4; j++) {
                const float p = __expf(s[i][j] - mnew);
                s[i][j] = p;
                rs += p;
            }
#pragma unroll
            for (int o = 8; o; o >>= 1)
                rs += __shfl_xor_sync(0xffffffffu, rs, o, 16);
            li[i] = li[i] * alpha + rs;
            mi[i] = mnew;
#pragma unroll
            for (int j = 0; j < 4; j++) acc[i][j] *= alpha;
        }

        __syncthreads();             // all K reads done before P overwrite
#pragma unroll
        for (int i = 0; i < 4; i++)
#pragma unroll
            for (int j = 0; j < 4; j++)
                Ks[(ty + 16 * i) * 65 + (tx + 16 * j)] = s[i][j];
        __syncthreads();

        // O += P @ V
#pragma unroll 4
        for (int k = 0; k < 64; k++) {
            float pv[4], vv[4];
#pragma unroll
            for (int i = 0; i < 4; i++) pv[i] = Ks[(ty + 16 * i) * 65 + k];
#pragma unroll
            for (int j = 0; j < 4; j++) vv[j] = Vs[k * 64 + tx + 16 * j];
#pragma unroll
            for (int i = 0; i < 4; i++)
#pragma unroll
                for (int j = 0; j < 4; j++)
                    acc[i][j] = fmaf(pv[i], vv[j], acc[i][j]);
        }
    }

    // epilogue: reference's view quirk — (B*H) buffer viewed as (H,B)
    const int b2 = bh & 1;
    const int h2 = bh >> 1;
#pragma unroll
    for (int i = 0; i < 4; i++) {
        const float inv = 1.f / li[i];
        const int t = qb + ty + 16 * i;
#pragma unroll
        for (int j = 0; j < 4; j++) {
            const int col = h2 * D_HEAD + tx + 16 * j;
            g_ov[(size_t)(b2 * T_ + t) * D_MODEL + col] = acc[i][j] * inv;
        }
    }
}

// ---------------- Residual already added in o_gemm; LayerNorm per row --------
__global__ __launch_bounds__(256) void ln_kernel(const float* __restrict__ gamma,
                                                 const float* __restrict__ beta,
                                                 float* __restrict__ out) {
    __shared__ float red[8];
    const int row = blockIdx.x;
    const int tid = threadIdx.x;
    const float* yrow = g_y + (size_t)row * D_MODEL;

    float4 x = *(const float4*)(yrow + tid * 4);
    float s = x.x + x.y + x.z + x.w;
#pragma unroll
    for (int o = 16; o; o >>= 1) s += __shfl_xor_sync(0xffffffffu, s, o);
    if ((tid & 31) == 0) red[tid >> 5] = s;
    __syncthreads();
    s = red[0] + red[1] + red[2] + red[3] + red[4] + red[5] + red[6] + red[7];
    const float mu = s * (1.0f / D_MODEL);

    const float d0 = x.x - mu, d1 = x.y - mu, d2 = x.z - mu, d3 = x.w - mu;
    float v = d0 * d0 + d1 * d1 + d2 * d2 + d3 * d3;
#pragma unroll
    for (int o = 16; o; o >>= 1) v += __shfl_xor_sync(0xffffffffu, v, o);
    __syncthreads();
    if ((tid & 31) == 0) red[tid >> 5] = v;
    __syncthreads();
    v = red[0] + red[1] + red[2] + red[3] + red[4] + red[5] + red[6] + red[7];
    const float rstd = rsqrtf(v * (1.0f / D_MODEL) + 1e-5f);

    float4 g = *(const float4*)(gamma + tid * 4);
    float4 b = *(const float4*)(beta + tid * 4);
    float4 o4;
    o4.x = d0 * rstd * g.x + b.x;
    o4.y = d1 * rstd * g.y + b.y;
    o4.z = d2 * rstd * g.z + b.z;
    o4.w = d3 * rstd * g.w + b.w;
    *(float4*)(out + (size_t)row * D_MODEL + tid * 4) = o4;
}

// -----------------------------------------------------------------------------
extern "C" void kernel_launch(void* const* d_in, const int* in_sizes, int n_in,
                              void* d_out, int out_size) {
    const float* inp   = (const float*)d_in[0];
    const float* W_qkv = (const float*)d_in[1];
    const float* b_qkv = (const float*)d_in[2];
    const float* W_o   = (const float*)d_in[3];
    const float* gamma = (const float*)d_in[4];
    const float* beta  = (const float*)d_in[5];
    float* out = (float*)d_out;

    cudaFuncSetAttribute(attn_kernel,
                         cudaFuncAttributeMaxDynamicSharedMemorySize, SMEM_ATTN);

    qkv_gemm<<<dim3(N_QKV / 128, M_TOK / 128), 256>>>(inp, W_qkv, b_qkv);
    attn_kernel<<<dim3(T_ / 64, B_ * N_HEAD), 256, SMEM_ATTN>>>();
    o_gemm<<<dim3(D_MODEL / 128, M_TOK / 128), 256>>>(W_o, inp);
    ln_kernel<<<M_TOK, 256>>>(gamma, beta, out);
}

// round 5
// speedup vs baseline: 3.0238x; 3.0238x over previous
#include <cuda_runtime.h>
#include <math.h>

#define D_MODEL 1024
#define N_HEAD  16
#define D_HEAD  64
#define B_      2
#define T_      2048
#define M_TOK   (B_ * T_)              // 4096
#define N_QKV   (3 * N_HEAD * D_HEAD)  // 3072

// ---------------- scratch (device globals; no allocation allowed) ------------
__device__ float g_q[B_ * N_HEAD * T_ * D_HEAD];   // (B,H,T,dh)
__device__ float g_k[B_ * N_HEAD * T_ * D_HEAD];
__device__ float g_v[B_ * N_HEAD * T_ * D_HEAD];
__device__ float g_ov[M_TOK * D_MODEL];            // attn_vec in (B,T,H*dh)
__device__ float g_y[M_TOK * D_MODEL];             // inp + attn_out

// ---------------- tf32 helpers ----------------------------------------------
__device__ __forceinline__ unsigned f2t(float x) {
    unsigned u;
    asm("cvt.rna.tf32.f32 %0, %1;" : "=r"(u) : "f"(x));
    return u;
}

__device__ __forceinline__ void mma8(float* c,
                                     unsigned a0, unsigned a1, unsigned a2, unsigned a3,
                                     unsigned b0, unsigned b1) {
    asm volatile(
        "mma.sync.aligned.m16n8k8.row.col.f32.tf32.tf32.f32 "
        "{%0,%1,%2,%3}, {%4,%5,%6,%7}, {%8,%9}, {%0,%1,%2,%3};\n"
        : "+f"(c[0]), "+f"(c[1]), "+f"(c[2]), "+f"(c[3])
        : "r"(a0), "r"(a1), "r"(a2), "r"(a3), "r"(b0), "r"(b1));
}

// =============================================================================
// GEMM: C[m,o] = A[m,:] . W[o,:] (+epilogue). block 128x128, 8 warps (2m x 4n),
// warp tile 64x32 (4x4 m16n8k8 atoms), k-step 32, tf32 fragments in smem.
// =============================================================================
#define GP 36   // smem row pad (words): 36 mod 32 == 4 -> conflict-free frags

__global__ __launch_bounds__(256) void qkv_gemm(const float* __restrict__ A,
                                                const float* __restrict__ W,
                                                const float* __restrict__ bias) {
    __shared__ unsigned As[128][GP];   // [m][k]
    __shared__ unsigned Bs[128][GP];   // [n][k]
    const int tid = threadIdx.x;
    const int m0 = blockIdx.y * 128, n0 = blockIdx.x * 128;
    const int w = tid >> 5, lane = tid & 31;
    const int g = lane >> 2, l = lane & 3;
    const int wm = (w >> 2) * 64, wn = (w & 3) * 32;
    const int lr = tid >> 3, lc = (tid & 7) * 4;

    float acc[4][4][4];
#pragma unroll
    for (int mi = 0; mi < 4; mi++)
#pragma unroll
        for (int ni = 0; ni < 4; ni++)
#pragma unroll
            for (int c = 0; c < 4; c++) acc[mi][ni][c] = 0.f;

    for (int kt = 0; kt < D_MODEL; kt += 32) {
#pragma unroll
        for (int p = 0; p < 4; p++) {
            const int r = lr + p * 32;
            float4 a4 = *(const float4*)(A + (size_t)(m0 + r) * D_MODEL + kt + lc);
            uint4 ua; ua.x = f2t(a4.x); ua.y = f2t(a4.y); ua.z = f2t(a4.z); ua.w = f2t(a4.w);
            *(uint4*)&As[r][lc] = ua;
            float4 b4 = *(const float4*)(W + (size_t)(n0 + r) * D_MODEL + kt + lc);
            uint4 ub; ub.x = f2t(b4.x); ub.y = f2t(b4.y); ub.z = f2t(b4.z); ub.w = f2t(b4.w);
            *(uint4*)&Bs[r][lc] = ub;
        }
        __syncthreads();
#pragma unroll
        for (int ka = 0; ka < 4; ka++) {
            const int kk = ka * 8;
            unsigned af[4][4], bf[4][2];
#pragma unroll
            for (int mi = 0; mi < 4; mi++) {
                const int r = wm + mi * 16 + g;
                af[mi][0] = As[r][kk + l];     af[mi][1] = As[r + 8][kk + l];
                af[mi][2] = As[r][kk + l + 4]; af[mi][3] = As[r + 8][kk + l + 4];
            }
#pragma unroll
            for (int ni = 0; ni < 4; ni++) {
                const int c = wn + ni * 8 + g;
                bf[ni][0] = Bs[c][kk + l]; bf[ni][1] = Bs[c][kk + l + 4];
            }
#pragma unroll
            for (int mi = 0; mi < 4; mi++)
#pragma unroll
                for (int ni = 0; ni < 4; ni++)
                    mma8(acc[mi][ni], af[mi][0], af[mi][1], af[mi][2], af[mi][3],
                         bf[ni][0], bf[ni][1]);
        }
        __syncthreads();
    }

    // epilogue: +bias, scatter into (B,H,T,dh) q/k/v
#pragma unroll
    for (int mi = 0; mi < 4; mi++) {
#pragma unroll
        for (int rs_ = 0; rs_ < 2; rs_++) {
            const int mm = m0 + wm + mi * 16 + g + rs_ * 8;
            const int b = mm >> 11, t = mm & (T_ - 1);
#pragma unroll
            for (int ni = 0; ni < 4; ni++) {
                const int o = n0 + wn + ni * 8 + 2 * l;
                float2 bb = *(const float2*)(bias + o);
                float2 v;
                v.x = acc[mi][ni][rs_ * 2]     + bb.x;
                v.y = acc[mi][ni][rs_ * 2 + 1] + bb.y;
                const int part = o >> 10, rem = o & 1023;
                const int h = rem >> 6, d = rem & 63;
                const size_t idx = ((size_t)(b * N_HEAD + h) * T_ + t) * D_HEAD + d;
                if (part == 0)      *(float2*)&g_q[idx] = v;
                else if (part == 1) *(float2*)&g_k[idx] = v;
                else                *(float2*)&g_v[idx] = v;
            }
        }
    }
}

__global__ __launch_bounds__(256) void o_gemm(const float* __restrict__ Wo,
                                              const float* __restrict__ inp) {
    __shared__ unsigned As[128][GP];
    __shared__ unsigned Bs[128][GP];
    const int tid = threadIdx.x;
    const int m0 = blockIdx.y * 128, n0 = blockIdx.x * 128;
    const int w = tid >> 5, lane = tid & 31;
    const int g = lane >> 2, l = lane & 3;
    const int wm = (w >> 2) * 64, wn = (w & 3) * 32;
    const int lr = tid >> 3, lc = (tid & 7) * 4;

    float acc[4][4][4];
#pragma unroll
    for (int mi = 0; mi < 4; mi++)
#pragma unroll
        for (int ni = 0; ni < 4; ni++)
#pragma unroll
            for (int c = 0; c < 4; c++) acc[mi][ni][c] = 0.f;

    for (int kt = 0; kt < D_MODEL; kt += 32) {
#pragma unroll
        for (int p = 0; p < 4; p++) {
            const int r = lr + p * 32;
            float4 a4 = *(const float4*)(g_ov + (size_t)(m0 + r) * D_MODEL + kt + lc);
            uint4 ua; ua.x = f2t(a4.x); ua.y = f2t(a4.y); ua.z = f2t(a4.z); ua.w = f2t(a4.w);
            *(uint4*)&As[r][lc] = ua;
            float4 b4 = *(const float4*)(Wo + (size_t)(n0 + r) * D_MODEL + kt + lc);
            uint4 ub; ub.x = f2t(b4.x); ub.y = f2t(b4.y); ub.z = f2t(b4.z); ub.w = f2t(b4.w);
            *(uint4*)&Bs[r][lc] = ub;
        }
        __syncthreads();
#pragma unroll
        for (int ka = 0; ka < 4; ka++) {
            const int kk = ka * 8;
            unsigned af[4][4], bf[4][2];
#pragma unroll
            for (int mi = 0; mi < 4; mi++) {
                const int r = wm + mi * 16 + g;
                af[mi][0] = As[r][kk + l];     af[mi][1] = As[r + 8][kk + l];
                af[mi][2] = As[r][kk + l + 4]; af[mi][3] = As[r + 8][kk + l + 4];
            }
#pragma unroll
            for (int ni = 0; ni < 4; ni++) {
                const int c = wn + ni * 8 + g;
                bf[ni][0] = Bs[c][kk + l]; bf[ni][1] = Bs[c][kk + l + 4];
            }
#pragma unroll
            for (int mi = 0; mi < 4; mi++)
#pragma unroll
                for (int ni = 0; ni < 4; ni++)
                    mma8(acc[mi][ni], af[mi][0], af[mi][1], af[mi][2], af[mi][3],
                         bf[ni][0], bf[ni][1]);
        }
        __syncthreads();
    }

    // epilogue: + residual inp, write g_y
#pragma unroll
    for (int mi = 0; mi < 4; mi++) {
#pragma unroll
        for (int rs_ = 0; rs_ < 2; rs_++) {
            const int mm = m0 + wm + mi * 16 + g + rs_ * 8;
#pragma unroll
            for (int ni = 0; ni < 4; ni++) {
                const int o = n0 + wn + ni * 8 + 2 * l;
                const size_t idx = (size_t)mm * D_MODEL + o;
                float2 r2 = *(const float2*)(inp + idx);
                float2 v;
                v.x = acc[mi][ni][rs_ * 2]     + r2.x;
                v.y = acc[mi][ni][rs_ * 2 + 1] + r2.y;
                *(float2*)&g_y[idx] = v;
            }
        }
    }
}

// =============================================================================
// Flash attention, tf32 mma. Q block 128, key block 64, 8 warps (4m x 2n),
// warp tile 32x32 (2x4 atoms). Softmax scale folded into Q at load.
// =============================================================================
#define QB 128
#define KB 64
#define AP 68   // pad: 68 mod 32 == 4 -> conflict-free frags

#define SMEM_ATTN ((size_t)((128 + 64 + 64 + 128) * AP + 256 + 3 * 128) * 4)

__global__ __launch_bounds__(256) void attn_kernel() {
    extern __shared__ unsigned smb[];
    unsigned* Qs = smb;                       // [128][AP]  (q, k=d)
    unsigned* Ks = Qs + 128 * AP;             // [64][AP]   (t, d)
    unsigned* Vs = Ks + 64 * AP;              // [64][AP]   (d, t)  transposed
    unsigned* Ps = Vs + 64 * AP;              // [128][AP]  (q, t)
    float* f_red = (float*)(Ps + 128 * AP);   // [2][128]
    float* f_m  = f_red + 256;                // [128]
    float* f_l  = f_m + 128;                  // [128]
    float* f_al = f_l + 128;                  // [128]

    const int bh = blockIdx.y;
    const int qb = blockIdx.x * QB;
    const float* Qg = g_q + (size_t)bh * T_ * D_HEAD;
    const float* Kg = g_k + (size_t)bh * T_ * D_HEAD;
    const float* Vg = g_v + (size_t)bh * T_ * D_HEAD;

    const int tid = threadIdx.x;
    const int w = tid >> 5, lane = tid & 31;
    const int g = lane >> 2, l = lane & 3;
    const int wm = (w >> 1) * 32;
    const int nwi = w & 1;
    const int wn = nwi * 32;

    if (tid < QB) { f_m[tid] = -1e30f; f_l[tid] = 0.f; }

    // load Q (128x64) with softmax scale folded in
#pragma unroll
    for (int it = 0; it < 8; it++) {
        const int fi = tid + it * 256;        // 2048 float4s
        const int r = fi >> 4, c = (fi & 15) * 4;
        float4 q4 = *(const float4*)(Qg + (size_t)(qb + r) * D_HEAD + c);
        uint4 u;
        u.x = f2t(q4.x * 0.125f); u.y = f2t(q4.y * 0.125f);
        u.z = f2t(q4.z * 0.125f); u.w = f2t(q4.w * 0.125f);
        *(uint4*)&Qs[r * AP + c] = u;
    }

    float oa[2][4][4];
#pragma unroll
    for (int mi = 0; mi < 2; mi++)
#pragma unroll
        for (int ni = 0; ni < 4; ni++)
#pragma unroll
            for (int c = 0; c < 4; c++) oa[mi][ni][c] = 0.f;

    for (int kb = 0; kb < T_; kb += KB) {
        __syncthreads();
        // K tile (64x64) [t][d]
#pragma unroll
        for (int it = 0; it < 4; it++) {
            const int fi = tid + it * 256;
            const int r = fi >> 4, c = (fi & 15) * 4;
            float4 k4 = *(const float4*)(Kg + (size_t)(kb + r) * D_HEAD + c);
            uint4 u; u.x = f2t(k4.x); u.y = f2t(k4.y); u.z = f2t(k4.z); u.w = f2t(k4.w);
            *(uint4*)&Ks[r * AP + c] = u;
        }
        // V tile transposed -> [d][t]
        {
            const int r = tid & 63, cb = (tid >> 6) * 16;
#pragma unroll
            for (int c4 = 0; c4 < 4; c4++) {
                float4 v4 = *(const float4*)(Vg + (size_t)(kb + r) * D_HEAD + cb + c4 * 4);
                const int d = cb + c4 * 4;
                Vs[(d + 0) * AP + r] = f2t(v4.x);
                Vs[(d + 1) * AP + r] = f2t(v4.y);
                Vs[(d + 2) * AP + r] = f2t(v4.z);
                Vs[(d + 3) * AP + r] = f2t(v4.w);
            }
        }
        __syncthreads();

        // S = Q @ K^T  (warp: rows wm..wm+31, cols wn..wn+31)
        float s[2][4][4];
#pragma unroll
        for (int mi = 0; mi < 2; mi++)
#pragma unroll
            for (int ni = 0; ni < 4; ni++)
#pragma unroll
                for (int c = 0; c < 4; c++) s[mi][ni][c] = 0.f;

#pragma unroll
        for (int ka = 0; ka < 8; ka++) {
            const int kk = ka * 8;
            unsigned qf[2][4], kf[4][2];
#pragma unroll
            for (int mi = 0; mi < 2; mi++) {
                const int r = wm + mi * 16 + g;
                qf[mi][0] = Qs[r * AP + kk + l];       qf[mi][1] = Qs[(r + 8) * AP + kk + l];
                qf[mi][2] = Qs[r * AP + kk + l + 4];   qf[mi][3] = Qs[(r + 8) * AP + kk + l + 4];
            }
#pragma unroll
            for (int ni = 0; ni < 4; ni++) {
                const int c = wn + ni * 8 + g;
                kf[ni][0] = Ks[c * AP + kk + l]; kf[ni][1] = Ks[c * AP + kk + l + 4];
            }
#pragma unroll
            for (int mi = 0; mi < 2; mi++)
#pragma unroll
                for (int ni = 0; ni < 4; ni++)
                    mma8(s[mi][ni], qf[mi][0], qf[mi][1], qf[mi][2], qf[mi][3],
                         kf[ni][0], kf[ni][1]);
        }

        // partial row max (per warp over its 32 cols)
#pragma unroll
        for (int mi = 0; mi < 2; mi++)
#pragma unroll
            for (int rs_ = 0; rs_ < 2; rs_++) {
                const int row = wm + mi * 16 + rs_ * 8 + g;
                float mx = s[mi][0][rs_ * 2];
#pragma unroll
                for (int ni = 0; ni < 4; ni++) {
                    mx = fmaxf(mx, s[mi][ni][rs_ * 2]);
                    mx = fmaxf(mx, s[mi][ni][rs_ * 2 + 1]);
                }
                mx = fmaxf(mx, __shfl_xor_sync(0xffffffffu, mx, 1));
                mx = fmaxf(mx, __shfl_xor_sync(0xffffffffu, mx, 2));
                if (l == 0) f_red[nwi * 128 + row] = mx;
            }
        __syncthreads();
        if (tid < QB) {
            const float mx = fmaxf(f_red[tid], f_red[128 + tid]);
            const float mo = f_m[tid];
            const float mn = fmaxf(mo, mx);
            f_al[tid] = __expf(mo - mn);
            f_m[tid] = mn;
        }
        __syncthreads();

        // exp, write P (tf32), partial row sums
#pragma unroll
        for (int mi = 0; mi < 2; mi++)
#pragma unroll
            for (int rs_ = 0; rs_ < 2; rs_++) {
                const int row = wm + mi * 16 + rs_ * 8 + g;
                const float mn = f_m[row];
                float rsum = 0.f;
#pragma unroll
                for (int ni = 0; ni < 4; ni++) {
                    const float p0 = __expf(s[mi][ni][rs_ * 2]     - mn);
                    const float p1 = __expf(s[mi][ni][rs_ * 2 + 1] - mn);
                    rsum += p0 + p1;
                    uint2 u; u.x = f2t(p0); u.y = f2t(p1);
                    *(uint2*)&Ps[row * AP + wn + ni * 8 + 2 * l] = u;
                }
                rsum += __shfl_xor_sync(0xffffffffu, rsum, 1);
                rsum += __shfl_xor_sync(0xffffffffu, rsum, 2);
                if (l == 0) f_red[nwi * 128 + row] = rsum;
            }
        __syncthreads();
        if (tid < QB)
            f_l[tid] = f_l[tid] * f_al[tid] + f_red[tid] + f_red[128 + tid];

        // rescale O accumulators
#pragma unroll
        for (int mi = 0; mi < 2; mi++)
#pragma unroll
            for (int rs_ = 0; rs_ < 2; rs_++) {
                const int row = wm + mi * 16 + rs_ * 8 + g;
                const float al = f_al[row];
#pragma unroll
                for (int ni = 0; ni < 4; ni++) {
                    oa[mi][ni][rs_ * 2]     *= al;
                    oa[mi][ni][rs_ * 2 + 1] *= al;
                }
            }

        // O += P @ V   (A = Ps[q][t], B = Vs[d][t])
#pragma unroll
        for (int ka = 0; ka < 8; ka++) {
            const int kk = ka * 8;
            unsigned pf[2][4], vf[4][2];
#pragma unroll
            for (int mi = 0; mi < 2; mi++) {
                const int r = wm + mi * 16 + g;
                pf[mi][0] = Ps[r * AP + kk + l];       pf[mi][1] = Ps[(r + 8) * AP + kk + l];
                pf[mi][2] = Ps[r * AP + kk + l + 4];   pf[mi][3] = Ps[(r + 8) * AP + kk + l + 4];
            }
#pragma unroll
            for (int ni = 0; ni < 4; ni++) {
                const int d = wn + ni * 8 + g;
                vf[ni][0] = Vs[d * AP + kk + l]; vf[ni][1] = Vs[d * AP + kk + l + 4];
            }
#pragma unroll
            for (int mi = 0; mi < 2; mi++)
#pragma unroll
                for (int ni = 0; ni < 4; ni++)
                    mma8(oa[mi][ni], pf[mi][0], pf[mi][1], pf[mi][2], pf[mi][3],
                         vf[ni][0], vf[ni][1]);
        }
    }
    __syncthreads();

    // epilogue with the reference's (H,B)->(B,T,H*dh) view permutation
    const int b2 = bh & 1, h2 = bh >> 1;
#pragma unroll
    for (int mi = 0; mi < 2; mi++)
#pragma unroll
        for (int rs_ = 0; rs_ < 2; rs_++) {
            const int row = wm + mi * 16 + rs_ * 8 + g;
            const float inv = 1.f / f_l[row];
            const int t = qb + row;
#pragma unroll
            for (int ni = 0; ni < 4; ni++) {
                const int col = h2 * D_HEAD + wn + ni * 8 + 2 * l;
                float2 v;
                v.x = oa[mi][ni][rs_ * 2]     * inv;
                v.y = oa[mi][ni][rs_ * 2 + 1] * inv;
                *(float2*)&g_ov[(size_t)(b2 * T_ + t) * D_MODEL + col] = v;
            }
        }
}

// ---------------- LayerNorm per row (residual already in g_y) ----------------
__global__ __launch_bounds__(256) void ln_kernel(const float* __restrict__ gamma,
                                                 const float* __restrict__ beta,
                                                 float* __restrict__ out) {
    __shared__ float red[8];
    const int row = blockIdx.x;
    const int tid = threadIdx.x;
    const float* yrow = g_y + (size_t)row * D_MODEL;

    float4 x = *(const float4*)(yrow + tid * 4);
    float s = x.x + x.y + x.z + x.w;
#pragma unroll
    for (int o = 16; o; o >>= 1) s += __shfl_xor_sync(0xffffffffu, s, o);
    if ((tid & 31) == 0) red[tid >> 5] = s;
    __syncthreads();
    s = red[0] + red[1] + red[2] + red[3] + red[4] + red[5] + red[6] + red[7];
    const float mu = s * (1.0f / D_MODEL);

    const float d0 = x.x - mu, d1 = x.y - mu, d2 = x.z - mu, d3 = x.w - mu;
    float v = d0 * d0 + d1 * d1 + d2 * d2 + d3 * d3;
#pragma unroll
    for (int o = 16; o; o >>= 1) v += __shfl_xor_sync(0xffffffffu, v, o);
    __syncthreads();
    if ((tid & 31) == 0) red[tid >> 5] = v;
    __syncthreads();
    v = red[0] + red[1] + red[2] + red[3] + red[4] + red[5] + red[6] + red[7];
    const float rstd = rsqrtf(v * (1.0f / D_MODEL) + 1e-5f);

    float4 gm = *(const float4*)(gamma + tid * 4);
    float4 bt = *(const float4*)(beta + tid * 4);
    float4 o4;
    o4.x = d0 * rstd * gm.x + bt.x;
    o4.y = d1 * rstd * gm.y + bt.y;
    o4.z = d2 * rstd * gm.z + bt.z;
    o4.w = d3 * rstd * gm.w + bt.w;
    *(float4*)(out + (size_t)row * D_MODEL + tid * 4) = o4;
}

// -----------------------------------------------------------------------------
extern "C" void kernel_launch(void* const* d_in, const int* in_sizes, int n_in,
                              void* d_out, int out_size) {
    const float* inp   = (const float*)d_in[0];
    const float* W_qkv = (const float*)d_in[1];
    const float* b_qkv = (const float*)d_in[2];
    const float* W_o   = (const float*)d_in[3];
    const float* gamma = (const float*)d_in[4];
    const float* beta  = (const float*)d_in[5];
    float* out = (float*)d_out;

    cudaFuncSetAttribute(attn_kernel,
                         cudaFuncAttributeMaxDynamicSharedMemorySize, (int)SMEM_ATTN);

    qkv_gemm<<<dim3(N_QKV / 128, M_TOK / 128), 256>>>(inp, W_qkv, b_qkv);
    attn_kernel<<<dim3(T_ / QB, B_ * N_HEAD), 256, SMEM_ATTN>>>();
    o_gemm<<<dim3(D_MODEL / 128, M_TOK / 128), 256>>>(W_o, inp);
    ln_kernel<<<M_TOK, 256>>>(gamma, beta, out);
}